// round 3
// baseline (speedup 1.0000x reference)
#include <cuda_runtime.h>
#include <cstdint>

#define S_TOTAL 524288
#define ROW_F 48          // N_OBJ * N_PROP floats per s-row

// out layout: action_probs (2, S, 3) then p_values (2, 28, S)
__global__ __launch_bounds__(256)
void ump_kernel(const float* __restrict__ x,
                const float* __restrict__ action,
                const unsigned char* __restrict__ mask,
                const float* __restrict__ pb,
                float* __restrict__ out)
{
    const size_t S = (size_t)S_TOTAL;
    int t = blockIdx.x * blockDim.x + threadIdx.x;
    int s0 = t * 4;
    if (s0 >= S_TOTAL) return;

    const float* row = x + (size_t)s0 * ROW_F;

    // agent (obj 0) props 0,1 for the 4 rows
    float2 v0[4];
#pragma unroll
    for (int i = 0; i < 4; i++)
        v0[i] = *reinterpret_cast<const float2*>(row + i * ROW_F);

    // both predicate flags are true -> combined interval
    float lb0 = pb[0], ub0 = pb[1], lb1 = pb[2], ub1 = pb[3];
    float lo = fmaxf(lb0, lb1);
    float hi = fminf(ub0, ub1);

    bool any_sat[4]     = {false, false, false, false};
    bool enemy_exist[4] = {true, true, true, true};

    float* __restrict__ pv = out + 6 * S;

#pragma unroll
    for (int p = 0; p < 7; p++) {
        float2 e[4];
#pragma unroll
        for (int i = 0; i < 4; i++)
            e[i] = *reinterpret_cast<const float2*>(row + i * ROW_F + (p + 1) * 6);

        float dd0[4], dd1[4];
#pragma unroll
        for (int i = 0; i < 4; i++) {
            dd0[i] = fabsf(v0[i].x - e[i].x);
            dd1[i] = fabsf(v0[i].y - e[i].y);
            any_sat[i] = any_sat[i]
                      || (dd0[i] >= lo && dd0[i] <= hi)
                      || (dd1[i] >= lo && dd1[i] <= hi);
            enemy_exist[i] = enemy_exist[i] && (e[i].y > 0.8f);
        }
        float4 d0 = make_float4(dd0[0], dd0[1], dd0[2], dd0[3]);
        float4 d1 = make_float4(dd1[0], dd1[1], dd1[2], dd1[3]);

        size_t r = (size_t)p * 4;
        // rows p*4+{0,1}=d0, p*4+{2,3}=d1; duplicated at +28 (second type slice)
        *reinterpret_cast<float4*>(pv + (r + 0)  * S + s0) = d0;
        *reinterpret_cast<float4*>(pv + (r + 1)  * S + s0) = d0;
        *reinterpret_cast<float4*>(pv + (r + 2)  * S + s0) = d1;
        *reinterpret_cast<float4*>(pv + (r + 3)  * S + s0) = d1;
        *reinterpret_cast<float4*>(pv + (r + 28) * S + s0) = d0;
        *reinterpret_cast<float4*>(pv + (r + 29) * S + s0) = d0;
        *reinterpret_cast<float4*>(pv + (r + 30) * S + s0) = d1;
        *reinterpret_cast<float4*>(pv + (r + 31) * S + s0) = d1;
    }

    // existence + action_probs
    bool m0 = mask[0] != 0;
    bool m1 = mask[1] != 0;
    float a0 = action[0], a1 = action[1], a2 = action[2];
    float an0 = a0 / (a0 + 1e-20f);
    float an1 = a1 / (a1 + 1e-20f);
    float an2 = a2 / (a2 + 1e-20f);

    float f[12];
#pragma unroll
    for (int i = 0; i < 4; i++) {
        bool agent_exist = v0[i].x > 0.8f;
        bool sat = any_sat[i] && (agent_exist == m0) && (enemy_exist[i] == m1);
        f[i * 3 + 0] = sat ? an0 : 0.0f;
        f[i * 3 + 1] = sat ? an1 : 0.0f;
        f[i * 3 + 2] = sat ? an2 : 0.0f;
    }
    // s0 % 4 == 0 -> byte offset s0*12 is 16B aligned
    float4* ap0 = reinterpret_cast<float4*>(out + (size_t)s0 * 3);
    float4* ap1 = reinterpret_cast<float4*>(out + 3 * S + (size_t)s0 * 3);
#pragma unroll
    for (int q = 0; q < 3; q++) {
        float4 val = make_float4(f[q * 4 + 0], f[q * 4 + 1], f[q * 4 + 2], f[q * 4 + 3]);
        ap0[q] = val;
        ap1[q] = val;
    }
}

extern "C" void kernel_launch(void* const* d_in, const int* in_sizes, int n_in,
                              void* d_out, int out_size)
{
    const float* x = (const float*)d_in[0];
    const float* action = (const float*)d_in[1];
    const unsigned char* mask = (const unsigned char*)d_in[2];
    const float* pb = (const float*)d_in[3];
    float* out = (float*)d_out;

    int threads = 256;
    int total_threads = S_TOTAL / 4;
    int blocks = (total_threads + threads - 1) / threads;
    ump_kernel<<<blocks, threads>>>(x, action, mask, pb, out);
}

// round 4
// speedup vs baseline: 1.5364x; 1.5364x over previous
#include <cuda_runtime.h>
#include <cstdint>

#define S_TOTAL 524288
#define ROW_F 48          // N_OBJ * N_PROP floats per s-row

// out layout: action_probs (2, S, 3) then p_values (2, 28, S)
__global__ __launch_bounds__(256)
void ump_kernel(const float* __restrict__ x,
                const float* __restrict__ action,
                const unsigned char* __restrict__ mask,
                const float* __restrict__ pb,
                float* __restrict__ out)
{
    const size_t S = (size_t)S_TOTAL;
    int t = blockIdx.x * blockDim.x + threadIdx.x;
    int s0 = t * 2;
    if (s0 >= S_TOTAL) return;

    const float* row0 = x + (size_t)s0 * ROW_F;
    const float* row1 = row0 + ROW_F;

    // load props 0,1 of all 8 objects for both rows (16 x LDG.64, front-batched)
    float2 va[8], vb[8];
#pragma unroll
    for (int j = 0; j < 8; j++) {
        va[j] = __ldcs(reinterpret_cast<const float2*>(row0 + j * 6));
        vb[j] = __ldcs(reinterpret_cast<const float2*>(row1 + j * 6));
    }

    // combined interval (both predicate flags true)
    float lb0 = pb[0], ub0 = pb[1], lb1 = pb[2], ub1 = pb[3];
    float lo = fmaxf(lb0, lb1);
    float hi = fminf(ub0, ub1);

    float* __restrict__ pv = out + 6 * S;

    bool any_a = false, any_b = false;
    bool ee_a = true, ee_b = true;

#pragma unroll
    for (int p = 0; p < 7; p++) {
        float a0 = fabsf(va[0].x - va[p + 1].x);
        float a1 = fabsf(va[0].y - va[p + 1].y);
        float b0 = fabsf(vb[0].x - vb[p + 1].x);
        float b1 = fabsf(vb[0].y - vb[p + 1].y);

        any_a = any_a || (a0 >= lo && a0 <= hi) || (a1 >= lo && a1 <= hi);
        any_b = any_b || (b0 >= lo && b0 <= hi) || (b1 >= lo && b1 <= hi);
        ee_a = ee_a && (va[p + 1].y > 0.8f);
        ee_b = ee_b && (vb[p + 1].y > 0.8f);

        float2 d0 = make_float2(a0, b0);   // prop-0 distances for s0, s0+1
        float2 d1 = make_float2(a1, b1);   // prop-1

        size_t r = (size_t)p * 4;
        // rows p*4+{0,1}=d0, p*4+{2,3}=d1; duplicated at +28 (second type slice)
        __stcs(reinterpret_cast<float2*>(pv + (r + 0)  * S + s0), d0);
        __stcs(reinterpret_cast<float2*>(pv + (r + 1)  * S + s0), d0);
        __stcs(reinterpret_cast<float2*>(pv + (r + 2)  * S + s0), d1);
        __stcs(reinterpret_cast<float2*>(pv + (r + 3)  * S + s0), d1);
        __stcs(reinterpret_cast<float2*>(pv + (r + 28) * S + s0), d0);
        __stcs(reinterpret_cast<float2*>(pv + (r + 29) * S + s0), d0);
        __stcs(reinterpret_cast<float2*>(pv + (r + 30) * S + s0), d1);
        __stcs(reinterpret_cast<float2*>(pv + (r + 31) * S + s0), d1);
    }

    // existence + action_probs
    bool m0 = mask[0] != 0;
    bool m1 = mask[1] != 0;
    float ac0 = action[0], ac1 = action[1], ac2 = action[2];
    float an0 = ac0 / (ac0 + 1e-20f);
    float an1 = ac1 / (ac1 + 1e-20f);
    float an2 = ac2 / (ac2 + 1e-20f);

    bool sat_a = any_a && ((va[0].x > 0.8f) == m0) && (ee_a == m1);
    bool sat_b = any_b && ((vb[0].x > 0.8f) == m0) && (ee_b == m1);

    // 6 contiguous floats starting at s0*3 (s0 even -> 8B aligned)
    float2 w01 = make_float2(sat_a ? an0 : 0.0f, sat_a ? an1 : 0.0f);
    float2 w23 = make_float2(sat_a ? an2 : 0.0f, sat_b ? an0 : 0.0f);
    float2 w45 = make_float2(sat_b ? an1 : 0.0f, sat_b ? an2 : 0.0f);

    float* ap0 = out + (size_t)s0 * 3;
    float* ap1 = ap0 + 3 * S;
    __stcs(reinterpret_cast<float2*>(ap0 + 0), w01);
    __stcs(reinterpret_cast<float2*>(ap0 + 2), w23);
    __stcs(reinterpret_cast<float2*>(ap0 + 4), w45);
    __stcs(reinterpret_cast<float2*>(ap1 + 0), w01);
    __stcs(reinterpret_cast<float2*>(ap1 + 2), w23);
    __stcs(reinterpret_cast<float2*>(ap1 + 4), w45);
}

extern "C" void kernel_launch(void* const* d_in, const int* in_sizes, int n_in,
                              void* d_out, int out_size)
{
    const float* x = (const float*)d_in[0];
    const float* action = (const float*)d_in[1];
    const unsigned char* mask = (const unsigned char*)d_in[2];
    const float* pb = (const float*)d_in[3];
    float* out = (float*)d_out;

    int threads = 256;
    int total_threads = S_TOTAL / 2;
    int blocks = (total_threads + threads - 1) / threads;
    ump_kernel<<<blocks, threads>>>(x, action, mask, pb, out);
}